// round 17
// baseline (speedup 1.0000x reference)
#include <cuda_runtime.h>
#include <math.h>

#define NN 4096
#define FF 64
#define HH 128
#define NHD 4
#define HD 32
#define LL 3
#define CC 7
#define MAXD 96
#define GB 128      // 32-row GEMM blocks

// ---------------- device scratch ----------------
// packed per node: [pair p: h[2p], h[2p+1], hh[2p], hh[2p+1]]  (256 floats/node)
__device__ __align__(16) float g_pack[NN * 256];
__device__ __align__(16) float g_sup[NN * HH];
__device__ __align__(16) float g_att[NN * HH];
__device__ __align__(16) float g_ssrc[NN * NHD];
__device__ __align__(16) float g_sdst[NN * NHD];
__device__ __align__(16) float g_S3[LL][HH];       // per-layer S, atomically accumulated
__device__ __align__(16) int   g_cols[NN * MAXD];
__device__ int   g_cnt[NN];
__device__ float g_dinv[NN];
__device__ __align__(16) float g_mpart[GB * HH];

// ---- register-tiled full-K GEMM: sW [k][col] (KD x 128), sB rows k-contiguous ----
template <int KD, int RS>
__device__ __forceinline__ void mm_full(const float* sW, const float* sB,
                                        float acc[4][4], int rt, int lane) {
#pragma unroll 4
    for (int k = 0; k < KD; k += 4) {
        float4 A0 = ((const float4*)sW)[(k + 0) * 32 + lane];
        float4 A1 = ((const float4*)sW)[(k + 1) * 32 + lane];
        float4 A2 = ((const float4*)sW)[(k + 2) * 32 + lane];
        float4 A3 = ((const float4*)sW)[(k + 3) * 32 + lane];
#pragma unroll
        for (int i = 0; i < 4; i++) {
            float4 bv = *(const float4*)(sB + (rt * 4 + i) * RS + k);
            acc[i][0] = fmaf(bv.x, A0.x, acc[i][0]);
            acc[i][1] = fmaf(bv.x, A0.y, acc[i][1]);
            acc[i][2] = fmaf(bv.x, A0.z, acc[i][2]);
            acc[i][3] = fmaf(bv.x, A0.w, acc[i][3]);
            acc[i][0] = fmaf(bv.y, A1.x, acc[i][0]);
            acc[i][1] = fmaf(bv.y, A1.y, acc[i][1]);
            acc[i][2] = fmaf(bv.y, A1.z, acc[i][2]);
            acc[i][3] = fmaf(bv.y, A1.w, acc[i][3]);
            acc[i][0] = fmaf(bv.z, A2.x, acc[i][0]);
            acc[i][1] = fmaf(bv.z, A2.y, acc[i][1]);
            acc[i][2] = fmaf(bv.z, A2.z, acc[i][2]);
            acc[i][3] = fmaf(bv.z, A2.w, acc[i][3]);
            acc[i][0] = fmaf(bv.w, A3.x, acc[i][0]);
            acc[i][1] = fmaf(bv.w, A3.y, acc[i][1]);
            acc[i][2] = fmaf(bv.w, A3.z, acc[i][2]);
            acc[i][3] = fmaf(bv.w, A3.w, acc[i][3]);
        }
    }
}

// ---- load attn_W[head][k][d] into sW2[k][col=head*32+d] (4096 float4) ----
__device__ __forceinline__ void load_attnW(float* sW2, const float* __restrict__ aW,
                                           int tid) {
    for (int i4 = tid; i4 < 4096; i4 += 256) {
        int k = i4 >> 5, colq = i4 & 31;
        ((float4*)sW2)[i4] = *(const float4*)(aW + (colq >> 3) * (HH * HD)
                                              + k * HD + ((colq & 7) << 2));
    }
}

// ---- hh epilogue+GEMM: hh = sB @ sW2 + Wb -> g_pack hh slots; ssrc/sdst/S-atomics --
__device__ __forceinline__ void hh_phase(const float* sW2, const float* sB, float* sP,
                                         int r0, float* __restrict__ Sl,
                                         const float* __restrict__ Wb,
                                         const float* __restrict__ al) {
    int tid = threadIdx.x, lane = tid & 31, rt = tid >> 5;
    float acc[4][4];
#pragma unroll
    for (int i = 0; i < 4; i++)
#pragma unroll
        for (int j = 0; j < 4; j++) acc[i][j] = 0.0f;
    mm_full<HH, HH>(sW2, sB, acc, rt, lane);
    int col0 = lane * 4;
    int head = col0 >> 5;
    float4 wb = *(const float4*)(Wb + col0);
    float4 as = *(const float4*)(al + head * 64 + (col0 & 31));
    float4 ad = *(const float4*)(al + head * 64 + 32 + (col0 & 31));
    float cs0 = 0.f, cs1 = 0.f, cs2 = 0.f, cs3 = 0.f;
#pragma unroll
    for (int i = 0; i < 4; i++) {
        int r = r0 + rt * 4 + i;
        float v0 = acc[i][0] + wb.x, v1 = acc[i][1] + wb.y;
        float v2 = acc[i][2] + wb.z, v3 = acc[i][3] + wb.w;
        int base = r * 256 + col0 * 2;
        *(float2*)(g_pack + base + 2) = make_float2(v0, v1);
        *(float2*)(g_pack + base + 6) = make_float2(v2, v3);
        cs0 += v0; cs1 += v1; cs2 += v2; cs3 += v3;
        float vs = v0 * as.x + v1 * as.y + v2 * as.z + v3 * as.w;
        float vd = v0 * ad.x + v1 * ad.y + v2 * ad.z + v3 * ad.w;
        vs += __shfl_xor_sync(0xffffffffu, vs, 1);
        vs += __shfl_xor_sync(0xffffffffu, vs, 2);
        vs += __shfl_xor_sync(0xffffffffu, vs, 4);
        vd += __shfl_xor_sync(0xffffffffu, vd, 1);
        vd += __shfl_xor_sync(0xffffffffu, vd, 2);
        vd += __shfl_xor_sync(0xffffffffu, vd, 4);
        if ((lane & 7) == 0) {
            g_ssrc[r * NHD + head] = vs;
            g_sdst[r * NHD + head] = vd;
        }
    }
    *(float4*)(sP + rt * HH + col0) = make_float4(cs0, cs1, cs2, cs3);
    __syncthreads();
    if (tid < HH) {
        float s = 0.0f;
#pragma unroll
        for (int w = 0; w < 8; w++) s += sP[w * HH + tid];
        atomicAdd(Sl + tid, s);
    }
}

// ---------------- 1) edge-list build (+ zero ALL S accumulators) ----------------
__global__ void k_build(const float* __restrict__ adj) {
    if (blockIdx.x == 0) {
        for (int i = threadIdx.x; i < LL * HH; i += 256)   // FIX: cover all 384
            ((float*)g_S3)[i] = 0.0f;
    }
    int warp = (blockIdx.x * blockDim.x + threadIdx.x) >> 5;
    int lane = threadIdx.x & 31;
    const float4* row = (const float4*)(adj + (size_t)warp * NN);
    int base = warp * MAXD;
    int cnt = 0;
    for (int c0 = 0; c0 < NN / 4; c0 += 32) {
        float4 v = row[c0 + lane];
        float vals[4] = {v.x, v.y, v.z, v.w};
#pragma unroll
        for (int k = 0; k < 4; k++) {
            unsigned m = __ballot_sync(0xffffffffu, vals[k] > 0.0f);
            if (vals[k] > 0.0f) {
                int pos = cnt + __popc(m & ((1u << lane) - 1u));
                if (pos < MAXD) g_cols[base + pos] = (c0 + lane) * 4 + k;
            }
            cnt += __popc(m);
        }
    }
    if (lane == 0) {
        if (cnt > MAXD) cnt = MAXD;
        g_cnt[warp] = cnt;
        g_dinv[warp] = rsqrtf((float)cnt + 1.0f);
    }
}

// ---------------- 2) fused encoder GEMM + hh(layer0), full-W smem ----------------
__global__ void k_enc_hh(const float* __restrict__ x,
                         const float* __restrict__ W,
                         const float* __restrict__ b,
                         const float* __restrict__ aW0,
                         const float* __restrict__ aWb0,
                         const float* __restrict__ aa0) {
    extern __shared__ float sm[];
    float* sWe = sm;
    float* sW2 = sm + 8192;
    float* xs  = sm + 24576;
    float* sB  = sm + 26624;
    float* sP  = sm + 30720;
    int tid = threadIdx.x, lane = tid & 31, rt = tid >> 5;
    int blk = blockIdx.x, r0 = blk * 32;
    for (int i4 = tid; i4 < 2048; i4 += 256)
        ((float4*)sWe)[i4] = ((const float4*)W)[i4];
    load_attnW(sW2, aW0, tid);
    for (int i4 = tid; i4 < 512; i4 += 256)
        ((float4*)xs)[i4] = ((const float4*)(x + r0 * FF))[i4];
    __syncthreads();
    float acc[4][4];
#pragma unroll
    for (int i = 0; i < 4; i++)
#pragma unroll
        for (int j = 0; j < 4; j++) acc[i][j] = 0.0f;
    mm_full<FF, FF>(sWe, xs, acc, rt, lane);
    int col0 = lane * 4;
    float4 bb = *(const float4*)(b + col0);
#pragma unroll
    for (int i = 0; i < 4; i++) {
        int r = r0 + rt * 4 + i;
        float4 v = make_float4(fmaxf(acc[i][0] + bb.x, 0.0f),
                               fmaxf(acc[i][1] + bb.y, 0.0f),
                               fmaxf(acc[i][2] + bb.z, 0.0f),
                               fmaxf(acc[i][3] + bb.w, 0.0f));
        *(float4*)(sB + (rt * 4 + i) * HH + col0) = v;
        int base = r * 256 + col0 * 2;
        *(float2*)(g_pack + base + 0) = make_float2(v.x, v.y);
        *(float2*)(g_pack + base + 4) = make_float2(v.z, v.w);
    }
    __syncthreads();
    hh_phase(sW2, sB, sP, r0, (float*)g_S3, aWb0, aa0);
}

// ---------------- 3) sparse: 8 nodes/block, 32 thr/node, 4 channels/thread ------
__global__ void __launch_bounds__(256)
k_sparse(const float* __restrict__ abl, const float* __restrict__ Sl) {
    int tid = threadIdx.x;
    int w = tid >> 5;        // node slot 0..7
    int t = tid & 31;        // thread within node
    int n = blockIdx.x * 8 + w;
    int head = t >> 3;       // channels 4t..4t+3 share head
    __shared__ int   cols_s[8][MAXD];   // stores j*64 (float4 base index)
    __shared__ float dinv_s[8][MAXD];
    __shared__ float w_s[8][MAXD * NHD];
    __shared__ float ss[8][NHD];
    const float4* pk = (const float4*)g_pack;
    int E = g_cnt[n];
    if (t < NHD) ss[w][t] = g_ssrc[n * NHD + t] + abl[t];
    for (int e = t; e < E; e += 32) {
        int j = g_cols[n * MAXD + e];
        cols_s[w][e] = j * 64;
        dinv_s[w][e] = g_dinv[j];
    }
    __syncthreads();
    for (int idx = t; idx < E * NHD; idx += 32) {
        int e = idx >> 2, h2 = idx & 3;
        w_s[w][idx] = expf(ss[w][h2] + g_sdst[(cols_s[w][e] >> 4) + h2]) - 1.0f;
    }
    __syncthreads();
    float di = g_dinv[n];
    int s0 = 2 * t;          // first pack slot
    float4 ha = pk[n * 64 + s0];
    float4 hb = pk[n * 64 + s0 + 1];
    float4 accg = make_float4(di * ha.x, di * ha.y, di * hb.x, di * hb.y);
    float4 acca = *(const float4*)(Sl + 4 * t);
    float denom = (float)NN;
    const int* cl = cols_s[w];
    const float* dv = dinv_s[w];
    const float* wv = w_s[w];
    int e = 0;
    for (; e + 2 <= E; e += 2) {
        int b0 = cl[e], b1 = cl[e + 1];
        float4 p0 = pk[b0 + s0];
        float4 p1 = pk[b0 + s0 + 1];
        float4 p2 = pk[b1 + s0];
        float4 p3 = pk[b1 + s0 + 1];
        float d0 = dv[e], d1 = dv[e + 1];
        float w0 = wv[e * 4 + head], w1 = wv[(e + 1) * 4 + head];
        accg.x += d0 * p0.x; accg.y += d0 * p0.y;
        accg.z += d0 * p1.x; accg.w += d0 * p1.y;
        accg.x += d1 * p2.x; accg.y += d1 * p2.y;
        accg.z += d1 * p3.x; accg.w += d1 * p3.y;
        acca.x += w0 * p0.z; acca.y += w0 * p0.w;
        acca.z += w0 * p1.z; acca.w += w0 * p1.w;
        acca.x += w1 * p2.z; acca.y += w1 * p2.w;
        acca.z += w1 * p3.z; acca.w += w1 * p3.w;
        denom += w0 + w1;
    }
    if (e < E) {
        int b0 = cl[e];
        float4 p0 = pk[b0 + s0];
        float4 p1 = pk[b0 + s0 + 1];
        float d0 = dv[e];
        float w0 = wv[e * 4 + head];
        accg.x += d0 * p0.x; accg.y += d0 * p0.y;
        accg.z += d0 * p1.x; accg.w += d0 * p1.y;
        acca.x += w0 * p0.z; acca.y += w0 * p0.w;
        acca.z += w0 * p1.z; acca.w += w0 * p1.w;
        denom += w0;
    }
    float inv = 1.0f / denom;
    *(float4*)(g_sup + n * HH + 4 * t) =
        make_float4(di * accg.x, di * accg.y, di * accg.z, di * accg.w);
    *(float4*)(g_att + n * HH + 4 * t) =
        make_float4(acca.x * inv, acca.y * inv, acca.z * inv, acca.w * inv);
}

// ---------------- 4) fused combine GEMM + next-layer hh GEMM (full-W smem) -------
__global__ void k_comb_hh(const float* __restrict__ Wl,
                          const float* __restrict__ bl,
                          const float* __restrict__ aWn,
                          const float* __restrict__ aWbn,
                          const float* __restrict__ aan,
                          float* __restrict__ Sl) {
    extern __shared__ float sm[];
    float* sW1 = sm;
    float* sW2 = sm + 16384;
    float* sB  = sm + 32768;
    float* sP  = sm + 36864;
    int tid = threadIdx.x, lane = tid & 31, rt = tid >> 5;
    int blk = blockIdx.x, r0 = blk * 32;
    for (int i4 = tid; i4 < 4096; i4 += 256)
        ((float4*)sW1)[i4] = ((const float4*)Wl)[i4];
    load_attnW(sW2, aWn, tid);
    for (int i4 = tid; i4 < 1024; i4 += 256)
        ((float4*)sB)[i4] = ((const float4*)(g_sup + r0 * HH))[i4];
    __syncthreads();
    float acc[4][4];
#pragma unroll
    for (int i = 0; i < 4; i++)
#pragma unroll
        for (int j = 0; j < 4; j++) acc[i][j] = 0.0f;
    mm_full<HH, HH>(sW1, sB, acc, rt, lane);
    int col0 = lane * 4;
    float4 bb = *(const float4*)(bl + col0);
    __syncthreads();
#pragma unroll
    for (int i = 0; i < 4; i++) {
        int r = r0 + rt * 4 + i;
        float4 at = *(const float4*)(g_att + r * HH + col0);
        float4 v;
        v.x = fmaxf(fmaxf(acc[i][0] + bb.x, 0.0f) + at.x, 0.0f);
        v.y = fmaxf(fmaxf(acc[i][1] + bb.y, 0.0f) + at.y, 0.0f);
        v.z = fmaxf(fmaxf(acc[i][2] + bb.z, 0.0f) + at.z, 0.0f);
        v.w = fmaxf(fmaxf(acc[i][3] + bb.w, 0.0f) + at.w, 0.0f);
        *(float4*)(sB + (rt * 4 + i) * HH + col0) = v;
        int base = r * 256 + col0 * 2;
        *(float2*)(g_pack + base + 0) = make_float2(v.x, v.y);
        *(float2*)(g_pack + base + 4) = make_float2(v.z, v.w);
    }
    __syncthreads();
    hh_phase(sW2, sB, sP, r0, Sl, aWbn, aan);
}

// ---------------- 5) fused final combine + classifier head + mean partials -------
__global__ void k_comb_head(const float* __restrict__ Wl,
                            const float* __restrict__ bl,
                            const float* __restrict__ W1, const float* __restrict__ b1,
                            const float* __restrict__ W2, const float* __restrict__ b2,
                            float* __restrict__ out_logits, float* __restrict__ out_h) {
    extern __shared__ float sm[];
    float* sW1 = sm;
    float* sB  = sm + 16384;
    int tid = threadIdx.x, lane = tid & 31, rt = tid >> 5;
    int blk = blockIdx.x, r0 = blk * 32;
    for (int i4 = tid; i4 < 4096; i4 += 256)
        ((float4*)sW1)[i4] = ((const float4*)Wl)[i4];
    for (int i4 = tid; i4 < 1024; i4 += 256)
        ((float4*)sB)[i4] = ((const float4*)(g_sup + r0 * HH))[i4];
    __syncthreads();
    float acc[4][4];
#pragma unroll
    for (int i = 0; i < 4; i++)
#pragma unroll
        for (int j = 0; j < 4; j++) acc[i][j] = 0.0f;
    mm_full<HH, HH>(sW1, sB, acc, rt, lane);
    int col0 = lane * 4;
    float4 bb = *(const float4*)(bl + col0);
    __syncthreads();
#pragma unroll
    for (int i = 0; i < 4; i++) {
        int r = r0 + rt * 4 + i;
        float4 at = *(const float4*)(g_att + r * HH + col0);
        float4 v;
        v.x = fmaxf(fmaxf(acc[i][0] + bb.x, 0.0f) + at.x, 0.0f);
        v.y = fmaxf(fmaxf(acc[i][1] + bb.y, 0.0f) + at.y, 0.0f);
        v.z = fmaxf(fmaxf(acc[i][2] + bb.z, 0.0f) + at.z, 0.0f);
        v.w = fmaxf(fmaxf(acc[i][3] + bb.w, 0.0f) + at.w, 0.0f);
        *(float4*)(sB + (rt * 4 + i) * HH + col0) = v;
        *(float4*)(out_h + r * HH + col0) = v;
    }
    __syncthreads();
    if (tid < HH) {
        float s = 0.0f;
#pragma unroll 8
        for (int r = 0; r < 32; r++) s += sB[r * HH + tid];
        g_mpart[blk * HH + tid] = s;
    }
    {
        int c6 = tid & 63, rg = tid >> 6;
        float a8[8];
#pragma unroll
        for (int i = 0; i < 8; i++) a8[i] = b1[c6];
        for (int k = 0; k < HH; k++) {
            float wvv = W1[k * 64 + c6];
#pragma unroll
            for (int i = 0; i < 8; i++)
                a8[i] += sB[(rg * 8 + i) * HH + k] * wvv;
        }
        __syncthreads();
#pragma unroll
        for (int i = 0; i < 8; i++)
            sW1[(rg * 8 + i) * 64 + c6] = fmaxf(a8[i], 0.0f);
    }
    __syncthreads();
    if (tid < 32 * CC) {
        int r = tid / CC, q = tid - r * CC;
        float a = b2[q];
#pragma unroll 16
        for (int k = 0; k < 64; k++) a += sW1[r * 64 + k] * W2[k * CC + q];
        out_logits[(r0 + r) * CC + q] = a;
    }
}

// ---------------- 6) contagion head ----------------
__global__ void k_cont(const float* __restrict__ W1, const float* __restrict__ b1,
                       const float* __restrict__ W2, const float* __restrict__ b2,
                       float* __restrict__ out_c) {
    __shared__ float ms[HH];
    __shared__ float t1[64];
    int c = threadIdx.x;
    float s = 0.0f;
    for (int b = 0; b < GB; b++) s += g_mpart[b * HH + c];
    ms[c] = s * (1.0f / (float)NN);
    __syncthreads();
    if (c < 64) {
        float a = b1[c];
#pragma unroll 16
        for (int k = 0; k < HH; k++) a += ms[k] * W1[k * 64 + c];
        t1[c] = fmaxf(a, 0.0f);
    }
    __syncthreads();
    if (c == 0) {
        float a = b2[0];
        for (int k = 0; k < 64; k++) a += t1[k] * W2[k];
        out_c[0] = a;
    }
}

extern "C" void kernel_launch(void* const* d_in, const int* in_sizes, int n_in,
                              void* d_out, int out_size) {
    const float* x      = (const float*)d_in[0];
    const float* adj    = (const float*)d_in[1];
    const float* enc_W  = (const float*)d_in[2];
    const float* enc_b  = (const float*)d_in[3];
    const float* gcn_W  = (const float*)d_in[4];
    const float* gcn_b  = (const float*)d_in[5];
    const float* attn_W = (const float*)d_in[6];
    const float* attn_Wb= (const float*)d_in[7];
    const float* attn_a = (const float*)d_in[8];
    const float* attn_ab= (const float*)d_in[9];
    const float* cls_W1 = (const float*)d_in[10];
    const float* cls_b1 = (const float*)d_in[11];
    const float* cls_W2 = (const float*)d_in[12];
    const float* cls_b2 = (const float*)d_in[13];
    const float* con_W1 = (const float*)d_in[14];
    const float* con_b1 = (const float*)d_in[15];
    const float* con_W2 = (const float*)d_in[16];
    const float* con_b2 = (const float*)d_in[17];

    float* out = (float*)d_out;
    float* out_logits = out;
    float* out_h      = out + NN * CC;
    float* out_c      = out + NN * CC + NN * HH;

    static int attr_done = 0;
    if (!attr_done) {
        cudaFuncSetAttribute(k_enc_hh,   cudaFuncAttributeMaxDynamicSharedMemorySize, 31744 * 4);
        cudaFuncSetAttribute(k_comb_hh,  cudaFuncAttributeMaxDynamicSharedMemorySize, 37888 * 4);
        cudaFuncSetAttribute(k_comb_head,cudaFuncAttributeMaxDynamicSharedMemorySize, 20480 * 4);
        attr_done = 1;
    }

    float* S3 = nullptr;
    cudaGetSymbolAddress((void**)&S3, g_S3);

    k_build<<<NN / 8, 256>>>(adj);
    k_enc_hh<<<GB, 256, 31744 * 4>>>(x, enc_W, enc_b, attn_W, attn_Wb, attn_a);

    for (int l = 0; l < LL; l++) {
        k_sparse<<<NN / 8, 256>>>(attn_ab + l * NHD, S3 + l * HH);
        if (l < LL - 1) {
            k_comb_hh<<<GB, 256, 37888 * 4>>>(gcn_W + l * HH * HH, gcn_b + l * HH,
                                              attn_W + (l + 1) * NHD * HH * HD,
                                              attn_Wb + (l + 1) * NHD * HD,
                                              attn_a + (l + 1) * NHD * 2 * HD,
                                              S3 + (l + 1) * HH);
        } else {
            k_comb_head<<<GB, 256, 20480 * 4>>>(gcn_W + l * HH * HH, gcn_b + l * HH,
                                                cls_W1, cls_b1, cls_W2, cls_b2,
                                                out_logits, out_h);
        }
    }
    k_cont<<<1, HH>>>(con_W1, con_b1, con_W2, con_b2, out_c);
}